// round 1
// baseline (speedup 1.0000x reference)
#include <cuda_runtime.h>
#include <cstdint>

// Problem constants
#define BB      512      // batch
#define TT      256      // time steps
#define D_IN    64
#define D_STATE 64
#define NN      2048     // neurons
#define D_OUT   10
#define KAUG    128      // D_IN + D_STATE

// Decomposition: 16 neuron-groups x 8 batch-groups = 128 persistent CTAs
#define NG      16
#define BG      8
#define NT      128      // neurons per CTA
#define BT      64       // batch rows per CTA
#define NCTAS   (NG * BG)
#define THREADS 256

// SMEM layout (floats). All offsets 16B aligned.
#define ENC_STRIDE 132
#define SDT_STRIDE 132
#define X_OFF    0                        // x_s:   [BT][KAUG]        = 8192
#define ENC_OFF  (X_OFF + BT * KAUG)      // enc_s: [NT][ENC_STRIDE]  = 16896
#define SDT_OFF  (ENC_OFF + NT * ENC_STRIDE)  // sdt_s: [64][SDT_STRIDE] = 8448
#define A_OFF    (SDT_OFF + D_STATE * SDT_STRIDE) // a_s: [BT][NT]    = 8192
#define DEC_OFF  (A_OFF + BT * NT)        // dec_s: [NT][D_OUT]       = 1280
#define SMEM_FLOATS (DEC_OFF + NT * D_OUT)
#define SMEM_BYTES  (SMEM_FLOATS * 4)

// Global scratch (static __device__ — no allocation)
__device__ float g_partials[NG][BB][D_STATE];   // per-neuron-group partial s
__device__ float g_ssum[2][BB * D_STATE];       // double-buffered reduced state
__device__ float g_ypart[NG][BB][D_OUT];        // per-group partial outputs

// Self-cleaning grid barrier state (count returns to 0 after every barrier;
// gen grows monotonically across graph replays — equality compare is wrap-safe)
__device__ unsigned g_count = 0;
__device__ volatile unsigned g_gen = 0;

__device__ __forceinline__ void gsync() {
    __syncthreads();
    if (threadIdx.x == 0) {
        __threadfence();
        unsigned gen = g_gen;                 // read BEFORE arriving
        unsigned prev = atomicAdd(&g_count, 1);
        if (prev == NCTAS - 1) {
            g_count = 0;
            __threadfence();
            g_gen = gen + 1;
        } else {
            while (g_gen == gen) { }
            __threadfence();
        }
    }
    __syncthreads();
}

// Packed f32x2 FMA (Blackwell sm_100+): d = a*b + c lanewise on two f32.
__device__ __forceinline__ unsigned long long fma2(unsigned long long a,
                                                   unsigned long long b,
                                                   unsigned long long c) {
    unsigned long long d;
    asm("fma.rn.f32x2 %0, %1, %2, %3;" : "=l"(d) : "l"(a), "l"(b), "l"(c));
    return d;
}

__device__ __forceinline__ float lanesum(unsigned long long v) {
    return __uint_as_float((unsigned)v) + __uint_as_float((unsigned)(v >> 32));
}

__global__ void __launch_bounds__(THREADS, 1)
nef_kernel(const float* __restrict__ seq,     // [B][T][D_IN]
           const float* __restrict__ enc,     // [NN][KAUG]
           const float* __restrict__ bias,    // [NN]
           const float* __restrict__ gain,    // [NN]
           const float* __restrict__ sdec,    // [NN][D_STATE]
           const float* __restrict__ dec,     // [NN][D_OUT]
           float* __restrict__ out)           // [B][D_OUT]
{
    extern __shared__ float smem[];
    float* x_s   = smem + X_OFF;
    float* enc_s = smem + ENC_OFF;
    float* sdt_s = smem + SDT_OFF;
    float* a_s   = smem + A_OFF;
    float* dec_s = smem + DEC_OFF;

    const int tid   = threadIdx.x;
    const int ni    = blockIdx.x & (NG - 1);
    const int bi    = blockIdx.x >> 4;
    const int nbase = ni * NT;
    const int bbase = bi * BT;
    const int tn    = tid & 31;   // lane  -> n = tn + 32*j  /  d = tn + 32*j
    const int tw    = tid >> 5;   // warp  -> b = tw*8 + i

    // ---- one-time weight staging into SMEM ----
    for (int idx = tid * 4; idx < NT * KAUG; idx += THREADS * 4) {
        int n = idx >> 7, k = idx & 127;
        float4 v = *(const float4*)&enc[(nbase + n) * KAUG + k];
        *(float4*)&enc_s[n * ENC_STRIDE + k] = v;
    }
    for (int idx = tid; idx < NT * D_STATE; idx += THREADS) {
        int n = idx >> 6, d = idx & 63;
        sdt_s[d * SDT_STRIDE + n] = sdec[(nbase + n) * D_STATE + d];
    }
    for (int idx = tid; idx < NT * D_OUT; idx += THREADS)
        dec_s[idx] = dec[nbase * D_OUT + idx];

    float gj[4], bj[4];
#pragma unroll
    for (int j = 0; j < 4; j++) {
        gj[j] = gain[nbase + tn + 32 * j];
        bj[j] = bias[nbase + tn + 32 * j];
    }

    // zero initial state buffer (each of 32768 threads writes one entry)
    g_ssum[0][blockIdx.x * THREADS + tid] = 0.0f;
    __syncthreads();
    gsync();

    for (int t = 0; t < TT; t++) {
        const int cur = t & 1;

        // ---- build x_aug tile: [BT][KAUG] = [u_t | s] ----
        for (int idx = tid * 4; idx < BT * KAUG; idx += THREADS * 4) {
            int b = idx >> 7, k = idx & 127;
            float4 v;
            if (k < D_IN)
                v = *(const float4*)&seq[((size_t)(bbase + b) * TT + t) * D_IN + k];
            else
                v = *(const float4*)&g_ssum[cur][(bbase + b) * D_STATE + (k - D_IN)];
            *(float4*)&x_s[b * KAUG + k] = v;
        }
        __syncthreads();

        // ---- GEMM1: a[b][n] = |gain*(x.e) + bias|, f32x2 over k ----
        {
            unsigned long long acc[8][4];
#pragma unroll
            for (int i = 0; i < 8; i++)
#pragma unroll
                for (int j = 0; j < 4; j++) acc[i][j] = 0ULL;

            const float* xb = x_s + (tw * 8) * KAUG;
            const float* e0 = enc_s + tn * ENC_STRIDE;

#pragma unroll 2
            for (int kk = 0; kk < KAUG; kk += 4) {
                ulonglong2 ev[4];
#pragma unroll
                for (int j = 0; j < 4; j++)
                    ev[j] = *(const ulonglong2*)(e0 + j * 32 * ENC_STRIDE + kk);
#pragma unroll
                for (int i = 0; i < 8; i++) {
                    ulonglong2 xv = *(const ulonglong2*)(xb + i * KAUG + kk);
#pragma unroll
                    for (int j = 0; j < 4; j++) {
                        acc[i][j] = fma2(xv.x, ev[j].x, acc[i][j]);
                        acc[i][j] = fma2(xv.y, ev[j].y, acc[i][j]);
                    }
                }
            }
#pragma unroll
            for (int i = 0; i < 8; i++)
#pragma unroll
                for (int j = 0; j < 4; j++) {
                    float v = lanesum(acc[i][j]);
                    v = fabsf(fmaf(gj[j], v, bj[j]));
                    a_s[(tw * 8 + i) * NT + tn + 32 * j] = v;
                }
        }
        __syncthreads();

        // ---- GEMM2: s_partial[b][d] = a[b][:] . SD[:, d], f32x2 over n ----
        {
            unsigned long long sacc[8][2];
#pragma unroll
            for (int i = 0; i < 8; i++) { sacc[i][0] = 0ULL; sacc[i][1] = 0ULL; }

            const float* ab = a_s + (tw * 8) * NT;
            const float* s0 = sdt_s + tn * SDT_STRIDE;

#pragma unroll 2
            for (int nn0 = 0; nn0 < NT; nn0 += 4) {
                ulonglong2 sv0 = *(const ulonglong2*)(s0 + nn0);
                ulonglong2 sv1 = *(const ulonglong2*)(s0 + 32 * SDT_STRIDE + nn0);
#pragma unroll
                for (int i = 0; i < 8; i++) {
                    ulonglong2 av = *(const ulonglong2*)(ab + i * NT + nn0);
                    sacc[i][0] = fma2(av.x, sv0.x, sacc[i][0]);
                    sacc[i][0] = fma2(av.y, sv0.y, sacc[i][0]);
                    sacc[i][1] = fma2(av.x, sv1.x, sacc[i][1]);
                    sacc[i][1] = fma2(av.y, sv1.y, sacc[i][1]);
                }
            }
#pragma unroll
            for (int i = 0; i < 8; i++) {
                g_partials[ni][bbase + tw * 8 + i][tn]      = lanesum(sacc[i][0]);
                g_partials[ni][bbase + tw * 8 + i][tn + 32] = lanesum(sacc[i][1]);
            }
        }

        if (t == TT - 1) {
            // partial decode of final activations (runs once)
            for (int idx = tid; idx < BT * D_OUT; idx += THREADS) {
                int b = idx / D_OUT, o = idx % D_OUT;
                float acc = 0.0f;
                for (int n = 0; n < NT; n++)
                    acc += a_s[b * NT + n] * dec_s[n * D_OUT + o];
                g_ypart[ni][bbase + b][o] = acc;
            }
        }
        gsync();

        if (t < TT - 1) {
            // ---- reduce phase: sum 16 partials -> next state buffer ----
            int idx = blockIdx.x * THREADS + tid;   // 0..32767 = b*64 + d
            float s = 0.0f;
            const float* p = &g_partials[0][0][0];
#pragma unroll
            for (int g = 0; g < NG; g++)
                s += p[g * (BB * D_STATE) + idx];
            g_ssum[1 - cur][idx] = s;
            gsync();
        }
    }

    // ---- final output reduction (only neuron-group 0 CTAs) ----
    if (ni == 0) {
        for (int idx = tid; idx < BT * D_OUT; idx += THREADS) {
            int b = idx / D_OUT, o = idx % D_OUT;
            float s = 0.0f;
#pragma unroll
            for (int g = 0; g < NG; g++)
                s += g_ypart[g][bbase + b][o];
            out[(bbase + b) * D_OUT + o] = s;
        }
    }
}

extern "C" void kernel_launch(void* const* d_in, const int* in_sizes, int n_in,
                              void* d_out, int out_size) {
    (void)in_sizes; (void)n_in; (void)out_size;
    cudaFuncSetAttribute(nef_kernel, cudaFuncAttributeMaxDynamicSharedMemorySize,
                         SMEM_BYTES);
    nef_kernel<<<NCTAS, THREADS, SMEM_BYTES>>>(
        (const float*)d_in[0],   // seq
        (const float*)d_in[1],   // encoders
        (const float*)d_in[2],   // bias
        (const float*)d_in[3],   // gain
        (const float*)d_in[4],   // state_decoders
        (const float*)d_in[5],   // decoders
        (float*)d_out);
}